// round 2
// baseline (speedup 1.0000x reference)
#include <cuda_runtime.h>

#define NB    4096
#define MAXK  128
#define NBLK  592
#define NTHR  512

// Precomputed tables (written by pwl_pre, read by pwl_main)
__device__ float  g_sx[MAXK];
__device__ float  g_a[MAXK];
__device__ float  g_b[MAXK];
__device__ float2 g_lut[NB];
__device__ float  g_x0;
__device__ float  g_scale;

// ---------------------------------------------------------------------------
// Precompute: sort breakpoints, build per-segment (a,b) with y = a + b*x,
// build a 4096-bucket direct-resolution LUT. Buckets within +/-1 of any
// breakpoint's bucket are flagged (NaN sentinel) -> main kernel falls back to
// an exact binary search. Single block.
// ---------------------------------------------------------------------------
__global__ void pwl_pre(const float* __restrict__ xp,
                        const float* __restrict__ slopes,
                        const float* __restrict__ biases,
                        int K) {
    __shared__ float s_xp[MAXK], s_sx[MAXK], s_a[MAXK], s_b[MAXK];
    __shared__ int   s_bb[MAXK];     // bucket index of each sorted breakpoint (monotone)
    __shared__ int   s_flag[NB];
    __shared__ float s_x0, s_scale;

    int t = threadIdx.x;

    if (t < K) s_xp[t] = xp[t];
    __syncthreads();

    // Rank sort (stable): O(K^2), K<=128
    if (t < K) {
        float v = s_xp[t];
        int r = 0;
        for (int j = 0; j < K; j++) {
            float w = s_xp[j];
            r += (w < v) || (w == v && j < t);
        }
        s_sx[r] = v;
    }
    __syncthreads();

    // betas recurrence + per-segment affine coefficients: y = a[i] + b[i]*x
    if (t == 0) {
        float beta = biases[0];
        for (int i = 0; i < K; i++) {
            float sl = slopes[i];
            s_a[i] = fmaf(-s_sx[i], sl, beta);
            s_b[i] = sl;
            if (i + 1 < K) beta = fmaf(s_sx[i + 1] - s_sx[i], sl, beta);
        }
        float range = s_sx[K - 1] - s_sx[0];
        s_x0 = s_sx[0];
        s_scale = (range > 0.0f) ? (float)NB / range : 0.0f;
        g_x0 = s_x0;
        g_scale = s_scale;
    }
    for (int i = t; i < NB; i += blockDim.x) s_flag[i] = 0;
    __syncthreads();

    float x0 = s_x0, scale = s_scale;

    if (scale <= 0.0f) {
        // Degenerate range: force fallback everywhere (exact search path).
        for (int i = t; i < NB; i += blockDim.x) s_flag[i] = 1;
    } else if (t < K) {
        // Same bucket-mapping expression as the main kernel (monotone in v).
        int bb = (int)((s_sx[t] - x0) * scale);
        bb = min(max(bb, 0), NB - 1);
        s_bb[t] = bb;
        if (bb > 0)      s_flag[bb - 1] = 1;   // benign same-value races
        s_flag[bb] = 1;
        if (bb < NB - 1) s_flag[bb + 1] = 1;
    }
    __syncthreads();

    // For an unflagged bucket b: every x mapping to b has
    //   pos = #{sx <= x} = #{j : bucket(sx_j) < b}   (exact, by monotonicity)
    // idx = clip(pos,1,K)-1. Binary search on the monotone int array s_bb.
    for (int bkt = t; bkt < NB; bkt += blockDim.x) {
        float2 e;
        if (s_flag[bkt]) {
            e.x = __int_as_float(0x7FC00000);   // NaN sentinel
            e.y = __int_as_float(0x7FC00000);
        } else {
            int lo = 0, hi = K;
            while (lo < hi) {
                int mid = (lo + hi) >> 1;
                if (s_bb[mid] < bkt) lo = mid + 1; else hi = mid;
            }
            int idx = min(max(lo, 1), K) - 1;
            e.x = s_a[idx];
            e.y = s_b[idx];
        }
        g_lut[bkt] = e;
    }
    for (int i = t; i < K; i += blockDim.x) {
        g_sx[i] = s_sx[i];
        g_a[i]  = s_a[i];
        g_b[i]  = s_b[i];
    }
}

// ---------------------------------------------------------------------------
// Main elementwise kernel
// ---------------------------------------------------------------------------
__device__ __forceinline__ float pwl_eval(float x, float x0, float scale,
                                          const float2* __restrict__ s_lut,
                                          const float*  __restrict__ s_sx,
                                          const float*  __restrict__ s_a,
                                          const float*  __restrict__ s_b,
                                          int K) {
    int bkt = (int)((x - x0) * scale);       // f2i saturates; out-of-range -> flagged edge buckets
    bkt = min(max(bkt, 0), NB - 1);
    float2 cb = s_lut[bkt];
    float aa = cb.x, bb = cb.y;
    if (bb != bb) {                          // NaN sentinel -> exact searchsorted-right
        int lo = 0, hi = K;
        while (lo < hi) {
            int mid = (lo + hi) >> 1;
            if (s_sx[mid] <= x) lo = mid + 1; else hi = mid;
        }
        int idx = min(max(lo, 1), K) - 1;
        aa = s_a[idx];
        bb = s_b[idx];
    }
    float y = fmaf(bb, x, aa);
    return fminf(fmaxf(y, 0.0f), 1.0f);
}

__global__ void __launch_bounds__(NTHR, 4)
pwl_main(const float* __restrict__ x, float* __restrict__ out, int n, int K) {
    __shared__ float2 s_lut[NB];
    __shared__ float  s_sx[MAXK], s_a[MAXK], s_b[MAXK];

    for (int i = threadIdx.x; i < NB; i += NTHR) s_lut[i] = g_lut[i];
    for (int i = threadIdx.x; i < MAXK; i += NTHR) {
        s_sx[i] = g_sx[i];
        s_a[i]  = g_a[i];
        s_b[i]  = g_b[i];
    }
    __syncthreads();

    const float x0 = g_x0, scale = g_scale;
    const int n4 = n >> 2;
    const float4* __restrict__ x4 = (const float4*)x;
    float4* __restrict__ o4 = (float4*)out;
    const int stride = gridDim.x * NTHR;

    #pragma unroll 2
    for (int i = blockIdx.x * NTHR + threadIdx.x; i < n4; i += stride) {
        float4 v = x4[i];
        float4 r;
        r.x = pwl_eval(v.x, x0, scale, s_lut, s_sx, s_a, s_b, K);
        r.y = pwl_eval(v.y, x0, scale, s_lut, s_sx, s_a, s_b, K);
        r.z = pwl_eval(v.z, x0, scale, s_lut, s_sx, s_a, s_b, K);
        r.w = pwl_eval(v.w, x0, scale, s_lut, s_sx, s_a, s_b, K);
        o4[i] = r;
    }

    // Scalar tail (n not divisible by 4)
    int rem = n & 3;
    if (blockIdx.x == 0 && threadIdx.x < rem) {
        int i = (n4 << 2) + threadIdx.x;
        out[i] = pwl_eval(x[i], x0, scale, s_lut, s_sx, s_a, s_b, K);
    }
}

// ---------------------------------------------------------------------------
extern "C" void kernel_launch(void* const* d_in, const int* in_sizes, int n_in,
                              void* d_out, int out_size) {
    const float* x      = (const float*)d_in[0];
    const float* xp     = (const float*)d_in[1];
    const float* slopes = (const float*)d_in[2];
    const float* biases = (const float*)d_in[3];
    int K = in_sizes[1];

    pwl_pre<<<1, 1024>>>(xp, slopes, biases, K);
    pwl_main<<<NBLK, NTHR>>>(x, (float*)d_out, out_size, K);
}

// round 4
// speedup vs baseline: 1.5764x; 1.5764x over previous
#include <cuda_runtime.h>

#define NB    2048
#define MAXK  128
#define NBLK  592
#define NTHR  512

// Precomputed tables (written by pwl_pre, read by pwl_main)
__device__ float4 g_lut4[NB];
__device__ float  g_sx[MAXK];
__device__ float  g_a[MAXK];
__device__ float  g_b[MAXK];
__device__ float  g_scale;
__device__ float  g_offs;

// ---------------------------------------------------------------------------
// Precompute (1 block): sort breakpoints, build y = a + b*x per segment, and a
// 2048-bucket LUT where each entry is {split, a_lo, b_lo, b_hi}:
//   - no effective breakpoint in bucket : split = +INF  (constant segment)
//   - one effective split               : branch-free compare in main kernel
//     (a_hi reconstructed from continuity: a_hi = a_lo + split*(b_lo - b_hi))
//   - >=2 effective splits (rare)       : split = NaN -> exact binary search
// ---------------------------------------------------------------------------
__global__ void pwl_pre(const float* __restrict__ xp,
                        const float* __restrict__ slopes,
                        const float* __restrict__ biases,
                        int K) {
    __shared__ float s_xp[MAXK], s_sx[MAXK], s_a[MAXK], s_b[MAXK];
    __shared__ int   s_bb[MAXK];
    __shared__ float sh_scale, sh_offs;

    int t = threadIdx.x;

    if (t < K) s_xp[t] = xp[t];
    __syncthreads();

    // Stable rank sort, O(K^2)
    if (t < K) {
        float v = s_xp[t];
        int r = 0;
        for (int j = 0; j < K; j++) {
            float w = s_xp[j];
            r += (w < v) || (w == v && j < t);
        }
        s_sx[r] = v;
    }
    __syncthreads();

    // betas recurrence -> per-segment affine y = a[i] + b[i]*x
    if (t == 0) {
        float beta = biases[0];
        for (int i = 0; i < K; i++) {
            float sl = slopes[i];
            s_a[i] = fmaf(-s_sx[i], sl, beta);
            s_b[i] = sl;
            if (i + 1 < K) beta = fmaf(s_sx[i + 1] - s_sx[i], sl, beta);
        }
        float range = s_sx[K - 1] - s_sx[0];
        float scale = (range > 0.0f) ? (float)NB / range : 0.0f;
        float offs  = -s_sx[0] * scale;
        sh_scale = scale;  sh_offs = offs;
        g_scale  = scale;  g_offs  = offs;
    }
    __syncthreads();

    // Bucket of each sorted breakpoint — IDENTICAL expression to main kernel
    // (monotone in x, so integer bucket logic below is exact).
    if (t < K) {
        int bb = (int)fmaf(s_sx[t], sh_scale, sh_offs);
        s_bb[t] = min(max(bb, 0), NB - 1);
    }
    __syncthreads();

    const float INF = __int_as_float(0x7F800000);
    const float QNAN = __int_as_float(0x7FC00000);

    for (int bkt = t; bkt < NB; bkt += blockDim.x) {
        // pos_left = #{j : bucket(sx_j) < bkt}; c = #{j : bucket == bkt}
        int pl = 0, c = 0;
        for (int j = 0; j < K; j++) {
            pl += (s_bb[j] < bkt);
            c  += (s_bb[j] == bkt);
        }
        int idx0 = min(max(pl, 1), K) - 1;

        // Walk in-bucket breakpoints (they are sorted indices pl..pl+c-1),
        // tracking effective (observable) idx transitions after clipping.
        int   cur = idx0, eff = 0;
        float ethr = 0.0f;
        for (int tt = 1; tt <= c; tt++) {
            int   j   = pl + tt - 1;
            int   ni  = min(max(pl + tt, 1), K) - 1;
            float thr = s_sx[j];
            if (ni != cur) {
                if (!(eff > 0 && thr == ethr)) { eff++; ethr = thr; }
                cur = ni;
            }
        }

        float4 e;
        if (eff == 0) {
            e = make_float4(INF, s_a[idx0], s_b[idx0], s_b[idx0]);
        } else if (eff == 1) {
            e = make_float4(ethr, s_a[idx0], s_b[idx0], s_b[cur]);
        } else {
            e = make_float4(QNAN, QNAN, QNAN, QNAN);   // rare fallback
        }
        g_lut4[bkt] = e;
    }

    for (int i = t; i < K; i += blockDim.x) {
        g_sx[i] = s_sx[i];
        g_a[i]  = s_a[i];
        g_b[i]  = s_b[i];
    }
}

// ---------------------------------------------------------------------------
// Main elementwise kernel — branch-free hot path, one LDS.128 per element.
// ---------------------------------------------------------------------------
__device__ __forceinline__ float pwl_fast(float x, float scale, float offs,
                                          const float4* __restrict__ s_lut,
                                          bool& bad) {
    int b = (int)fmaf(x, scale, offs);
    b = min(max(b, 0), NB - 1);
    float4 e = s_lut[b];
    bad = (e.x != e.x);                              // NaN sentinel
    bool  ge = (x >= e.x);                           // false for INF and NaN
    float bb = ge ? e.w : e.z;
    float aa = ge ? fmaf(e.x, e.z - e.w, e.y) : e.y; // continuity: a_hi
    float y  = fmaf(bb, x, aa);
    return fminf(fmaxf(y, 0.0f), 1.0f);
}

__device__ __noinline__ float pwl_fb(float x,
                                     const float* __restrict__ s_sx,
                                     const float* __restrict__ s_a,
                                     const float* __restrict__ s_b,
                                     int K) {
    int lo = 0, hi = K;
    while (lo < hi) {                                // searchsorted 'right'
        int mid = (lo + hi) >> 1;
        if (s_sx[mid] <= x) lo = mid + 1; else hi = mid;
    }
    int idx = min(max(lo, 1), K) - 1;
    float y = fmaf(s_b[idx], x, s_a[idx]);
    return fminf(fmaxf(y, 0.0f), 1.0f);
}

__global__ void __launch_bounds__(NTHR, 4)
pwl_main(const float* __restrict__ x, float* __restrict__ out, int n, int K) {
    __shared__ float4 s_lut[NB];
    __shared__ float  s_sx[MAXK], s_a[MAXK], s_b[MAXK];

    for (int i = threadIdx.x; i < NB; i += NTHR) s_lut[i] = g_lut4[i];
    for (int i = threadIdx.x; i < MAXK; i += NTHR) {
        s_sx[i] = g_sx[i];
        s_a[i]  = g_a[i];
        s_b[i]  = g_b[i];
    }
    __syncthreads();

    const float scale = g_scale, offs = g_offs;
    const int n4 = n >> 2;
    const float4* __restrict__ x4 = (const float4*)x;
    float4* __restrict__ o4 = (float4*)out;
    const int stride = gridDim.x * NTHR;

    #pragma unroll 2
    for (int i = blockIdx.x * NTHR + threadIdx.x; i < n4; i += stride) {
        float4 v = x4[i];
        bool b0, b1, b2, b3;
        float4 r;
        r.x = pwl_fast(v.x, scale, offs, s_lut, b0);
        r.y = pwl_fast(v.y, scale, offs, s_lut, b1);
        r.z = pwl_fast(v.z, scale, offs, s_lut, b2);
        r.w = pwl_fast(v.w, scale, offs, s_lut, b3);
        if (b0 | b1 | b2 | b3) {                     // rare: multi-split bucket
            if (b0) r.x = pwl_fb(v.x, s_sx, s_a, s_b, K);
            if (b1) r.y = pwl_fb(v.y, s_sx, s_a, s_b, K);
            if (b2) r.z = pwl_fb(v.z, s_sx, s_a, s_b, K);
            if (b3) r.w = pwl_fb(v.w, s_sx, s_a, s_b, K);
        }
        o4[i] = r;
    }

    // Scalar tail
    int rem = n & 3;
    if (blockIdx.x == 0 && threadIdx.x < rem) {
        int i = (n4 << 2) + threadIdx.x;
        bool bad;
        float y = pwl_fast(x[i], scale, offs, s_lut, bad);
        if (bad) y = pwl_fb(x[i], s_sx, s_a, s_b, K);
        out[i] = y;
    }
}

// ---------------------------------------------------------------------------
extern "C" void kernel_launch(void* const* d_in, const int* in_sizes, int n_in,
                              void* d_out, int out_size) {
    const float* x      = (const float*)d_in[0];
    const float* xp     = (const float*)d_in[1];
    const float* slopes = (const float*)d_in[2];
    const float* biases = (const float*)d_in[3];
    int K = in_sizes[1];

    pwl_pre<<<1, 1024>>>(xp, slopes, biases, K);
    pwl_main<<<NBLK, NTHR>>>(x, (float*)d_out, out_size, K);
}

// round 5
// speedup vs baseline: 1.5852x; 1.0056x over previous
#include <cuda_runtime.h>

#define NB       4096
#define MAXK     128
#define NBLK     592
#define NTHR     512
#define PREBLK   16
#define PRETHR   256
#define NB_SLICE (NB / PREBLK)

// Precomputed tables
__device__ float2 g_lutAB[NB];   // primary: {a, b} or {NaN, NaN} sentinel
__device__ float4 g_secA[NB];    // {t1, t2, a0, b0}  (t1=NaN -> >=3 splits)
__device__ float4 g_secB[NB];    // {a1, b1, a2, b2}
__device__ float  g_sx[MAXK];
__device__ float  g_a[MAXK];
__device__ float  g_b[MAXK];
__device__ float  g_scale;
__device__ float  g_offs;

// ---------------------------------------------------------------------------
// Precompute, 16 blocks. Each block redundantly sorts + builds coefficients,
// then fills its 256-bucket slice of the tables.
// Bucket mapping expression is IDENTICAL to the main kernel (monotone in x),
// so the integer counting below is exact.
// ---------------------------------------------------------------------------
__global__ void pwl_pre(const float* __restrict__ xp,
                        const float* __restrict__ slopes,
                        const float* __restrict__ biases,
                        int K) {
    __shared__ float s_xp[MAXK], s_sx[MAXK], s_a[MAXK], s_b[MAXK];
    __shared__ int   s_bb[MAXK];
    __shared__ float sh_scale, sh_offs;

    int t = threadIdx.x;

    if (t < K) s_xp[t] = xp[t];
    __syncthreads();

    // Stable rank sort, O(K^2)
    if (t < K) {
        float v = s_xp[t];
        int r = 0;
        for (int j = 0; j < K; j++) {
            float w = s_xp[j];
            r += (w < v) || (w == v && j < t);
        }
        s_sx[r] = v;
    }
    __syncthreads();

    // betas recurrence -> per-segment affine y = a[i] + b[i]*x
    if (t == 0) {
        float beta = biases[0];
        for (int i = 0; i < K; i++) {
            float sl = slopes[i];
            s_a[i] = fmaf(-s_sx[i], sl, beta);
            s_b[i] = sl;
            if (i + 1 < K) beta = fmaf(s_sx[i + 1] - s_sx[i], sl, beta);
        }
        float range = s_sx[K - 1] - s_sx[0];
        float scale = (range > 0.0f) ? (float)NB / range : 0.0f;
        float offs  = -s_sx[0] * scale;
        sh_scale = scale;  sh_offs = offs;
        if (blockIdx.x == 0) { g_scale = scale; g_offs = offs; }
    }
    __syncthreads();

    if (t < K) {
        int bb = (int)fmaf(s_sx[t], sh_scale, sh_offs);   // same expr as main
        s_bb[t] = min(max(bb, 0), NB - 1);
    }
    __syncthreads();

    const float INF  = __int_as_float(0x7F800000);
    const float QNAN = __int_as_float(0x7FC00000);
    const int   b0i  = blockIdx.x * NB_SLICE;

    for (int bkt = b0i + t; bkt < b0i + NB_SLICE; bkt += blockDim.x) {
        // pos_left = #{j : bucket(sx_j) < bkt}; c = #{j : bucket == bkt}
        int pl = 0, c = 0;
        for (int j = 0; j < K; j++) {
            pl += (s_bb[j] < bkt);
            c  += (s_bb[j] == bkt);
        }
        int idx0 = min(max(pl, 1), K) - 1;

        // Walk in-bucket breakpoints (sorted indices pl..pl+c-1), tracking
        // effective (observable after idx-clipping) transitions. Up to two
        // thresholds are representable exactly in the side tables.
        int   cur = idx0, eff = 0;
        int   g0 = idx0, g1 = idx0, g2 = idx0;
        float t1 = INF, t2 = INF, lastthr = 0.0f;
        for (int tt = 1; tt <= c; tt++) {
            int   ni  = min(max(pl + tt, 1), K) - 1;
            float thr = s_sx[pl + tt - 1];
            if (ni == cur) continue;
            if (eff >= 1 && thr == lastthr) {
                if (eff == 1) g1 = ni; else if (eff == 2) g2 = ni;
            } else {
                eff++;
                lastthr = thr;
                if (eff == 1)      { t1 = thr; g1 = ni; }
                else if (eff == 2) { t2 = thr; g2 = ni; }
            }
            cur = ni;
        }
        if (eff == 1) { g2 = g1; t2 = INF; }

        if (eff == 0) {
            g_lutAB[bkt] = make_float2(s_a[idx0], s_b[idx0]);
            g_secA[bkt]  = make_float4(INF, INF, s_a[idx0], s_b[idx0]);
            g_secB[bkt]  = make_float4(s_a[idx0], s_b[idx0], s_a[idx0], s_b[idx0]);
        } else if (eff <= 2) {
            g_lutAB[bkt] = make_float2(QNAN, QNAN);
            g_secA[bkt]  = make_float4(t1, t2, s_a[g0], s_b[g0]);
            g_secB[bkt]  = make_float4(s_a[g1], s_b[g1], s_a[g2], s_b[g2]);
        } else {
            g_lutAB[bkt] = make_float2(QNAN, QNAN);
            g_secA[bkt]  = make_float4(QNAN, QNAN, QNAN, QNAN);
            g_secB[bkt]  = make_float4(QNAN, QNAN, QNAN, QNAN);
        }
    }

    if (blockIdx.x == 0) {
        for (int i = t; i < K; i += blockDim.x) {
            g_sx[i] = s_sx[i];
            g_a[i]  = s_a[i];
            g_b[i]  = s_b[i];
        }
    }
}

// ---------------------------------------------------------------------------
// Main elementwise kernel — one LDS.64 + FMA + clamp per element hot path.
// ---------------------------------------------------------------------------
__device__ __forceinline__ float pwl_fast(float x, float scale, float offs,
                                          const float2* __restrict__ s_lut,
                                          bool& bad) {
    int b = (int)fmaf(x, scale, offs);
    b = min(max(b, 0), NB - 1);
    float2 e = s_lut[b];
    bad = (e.y != e.y);                       // NaN sentinel
    float y = fmaf(e.y, x, e.x);
    return fminf(fmaxf(y, 0.0f), 1.0f);
}

// Flagged-bucket path: up to two exact splits from the global side tables,
// binary search only for >=3 splits in a bucket (essentially never).
__device__ __noinline__ float pwl_slow(float x, float scale, float offs,
                                       const float* __restrict__ s_sx,
                                       const float* __restrict__ s_a,
                                       const float* __restrict__ s_b,
                                       int K) {
    int b = (int)fmaf(x, scale, offs);
    b = min(max(b, 0), NB - 1);
    float4 fA = __ldg(&g_secA[b]);
    float aa, bb;
    if (fA.x == fA.x) {
        float4 fB = __ldg(&g_secB[b]);
        int s = (x >= fA.x) + (x >= fA.y);    // 0,1,2 ; NaN/INF compare false
        aa = (s == 0) ? fA.z : ((s == 1) ? fB.x : fB.z);
        bb = (s == 0) ? fA.w : ((s == 1) ? fB.y : fB.w);
    } else {
        int lo = 0, hi = K;
        while (lo < hi) {                     // searchsorted 'right'
            int mid = (lo + hi) >> 1;
            if (s_sx[mid] <= x) lo = mid + 1; else hi = mid;
        }
        int idx = min(max(lo, 1), K) - 1;
        aa = s_a[idx];
        bb = s_b[idx];
    }
    float y = fmaf(bb, x, aa);
    return fminf(fmaxf(y, 0.0f), 1.0f);
}

__global__ void __launch_bounds__(NTHR, 4)
pwl_main(const float* __restrict__ x, float* __restrict__ out, int n, int K) {
    __shared__ float2 s_lut[NB];
    __shared__ float  s_sx[MAXK], s_a[MAXK], s_b[MAXK];

    for (int i = threadIdx.x; i < NB; i += NTHR) s_lut[i] = g_lutAB[i];
    for (int i = threadIdx.x; i < MAXK; i += NTHR) {
        s_sx[i] = g_sx[i];
        s_a[i]  = g_a[i];
        s_b[i]  = g_b[i];
    }
    __syncthreads();

    const float scale = g_scale, offs = g_offs;
    const int n4 = n >> 2;
    const float4* __restrict__ x4 = (const float4*)x;
    float4* __restrict__ o4 = (float4*)out;
    const int stride = gridDim.x * NTHR;

    #pragma unroll 2
    for (int i = blockIdx.x * NTHR + threadIdx.x; i < n4; i += stride) {
        float4 v = __ldcs(&x4[i]);
        bool b0, b1, b2, b3;
        float4 r;
        r.x = pwl_fast(v.x, scale, offs, s_lut, b0);
        r.y = pwl_fast(v.y, scale, offs, s_lut, b1);
        r.z = pwl_fast(v.z, scale, offs, s_lut, b2);
        r.w = pwl_fast(v.w, scale, offs, s_lut, b3);
        if (b0 | b1 | b2 | b3) {              // split bucket(s): exact side table
            if (b0) r.x = pwl_slow(v.x, scale, offs, s_sx, s_a, s_b, K);
            if (b1) r.y = pwl_slow(v.y, scale, offs, s_sx, s_a, s_b, K);
            if (b2) r.z = pwl_slow(v.z, scale, offs, s_sx, s_a, s_b, K);
            if (b3) r.w = pwl_slow(v.w, scale, offs, s_sx, s_a, s_b, K);
        }
        __stcs(&o4[i], r);
    }

    // Scalar tail
    int rem = n & 3;
    if (blockIdx.x == 0 && threadIdx.x < rem) {
        int i = (n4 << 2) + threadIdx.x;
        bool bad;
        float y = pwl_fast(x[i], scale, offs, s_lut, bad);
        if (bad) y = pwl_slow(x[i], scale, offs, s_sx, s_a, s_b, K);
        out[i] = y;
    }
}

// ---------------------------------------------------------------------------
extern "C" void kernel_launch(void* const* d_in, const int* in_sizes, int n_in,
                              void* d_out, int out_size) {
    const float* x      = (const float*)d_in[0];
    const float* xp     = (const float*)d_in[1];
    const float* slopes = (const float*)d_in[2];
    const float* biases = (const float*)d_in[3];
    int K = in_sizes[1];

    pwl_pre<<<PREBLK, PRETHR>>>(xp, slopes, biases, K);
    pwl_main<<<NBLK, NTHR>>>(x, (float*)d_out, out_size, K);
}

// round 6
// speedup vs baseline: 1.9126x; 1.2066x over previous
#include <cuda_runtime.h>

#define NB       4096
#define MAXK     128
#define MAXSID   128
#define NBLK     608
#define NTHR     512
#define PREBLK   16
#define PRETHR   256
#define NB_SLICE (NB / PREBLK)

// Precomputed tables
__device__ float2 g_lutAB[NB];          // {a,b} clean | {bitcast(sid), NaN} flagged
__device__ float4 g_side[2 * MAXSID];   // per sid: {t1,t2,a0,b0},{a1,b1,a2,b2}; t1=NaN => >=3 splits
__device__ float  g_sx[MAXK];
__device__ float  g_a[MAXK];
__device__ float  g_b[MAXK];
__device__ float  g_scale;
__device__ float  g_offs;

// ---------------------------------------------------------------------------
// Precompute, 16 blocks: each redundantly sorts + builds affine coefficients,
// fills its 256-bucket slice. Bucket expression is IDENTICAL to the main
// kernel (monotone in x) so integer counting is exact.
// ---------------------------------------------------------------------------
__global__ void pwl_pre(const float* __restrict__ xp,
                        const float* __restrict__ slopes,
                        const float* __restrict__ biases,
                        int K) {
    __shared__ float s_xp[MAXK], s_sx[MAXK], s_a[MAXK], s_b[MAXK];
    __shared__ int   s_bb[MAXK];
    __shared__ float sh_scale, sh_offs;

    int t = threadIdx.x;

    if (t < K) s_xp[t] = xp[t];
    __syncthreads();

    // Stable rank sort, O(K^2)
    if (t < K) {
        float v = s_xp[t];
        int r = 0;
        for (int j = 0; j < K; j++) {
            float w = s_xp[j];
            r += (w < v) || (w == v && j < t);
        }
        s_sx[r] = v;
    }
    __syncthreads();

    // betas recurrence -> per-segment affine y = a[i] + b[i]*x
    if (t == 0) {
        float beta = biases[0];
        for (int i = 0; i < K; i++) {
            float sl = slopes[i];
            s_a[i] = fmaf(-s_sx[i], sl, beta);
            s_b[i] = sl;
            if (i + 1 < K) beta = fmaf(s_sx[i + 1] - s_sx[i], sl, beta);
        }
        float range = s_sx[K - 1] - s_sx[0];
        float scale = (range > 0.0f) ? (float)NB / range : 0.0f;
        float offs  = -s_sx[0] * scale;
        sh_scale = scale;  sh_offs = offs;
        if (blockIdx.x == 0) { g_scale = scale; g_offs = offs; }
    }
    __syncthreads();

    if (t < K) {
        int bb = (int)fmaf(s_sx[t], sh_scale, sh_offs);   // same expr as main
        s_bb[t] = min(max(bb, 0), NB - 1);
    }
    __syncthreads();

    const float INF  = __int_as_float(0x7F800000);
    const float QNAN = __int_as_float(0x7FC00000);
    const int   base = blockIdx.x * NB_SLICE;

    for (int bkt = base + t; bkt < base + NB_SLICE; bkt += blockDim.x) {
        int pl = 0, c = 0;
        for (int j = 0; j < K; j++) {
            pl += (s_bb[j] < bkt);
            c  += (s_bb[j] == bkt);
        }
        int idx0 = min(max(pl, 1), K) - 1;

        // Walk in-bucket breakpoints, tracking effective (post-clip,
        // equal-threshold-merged) transitions. Up to two exactly encoded.
        int   cur = idx0, eff = 0;
        int   g0 = idx0, g1 = idx0, g2 = idx0;
        float t1 = INF, t2 = INF, lastthr = 0.0f;
        for (int tt = 1; tt <= c; tt++) {
            int   ni  = min(max(pl + tt, 1), K) - 1;
            float thr = s_sx[pl + tt - 1];
            if (ni == cur) continue;
            if (eff >= 1 && thr == lastthr) {
                if (eff == 1) g1 = ni; else if (eff == 2) g2 = ni;
            } else {
                eff++;
                lastthr = thr;
                if (eff == 1)      { t1 = thr; g1 = ni; }
                else if (eff == 2) { t2 = thr; g2 = ni; }
            }
            cur = ni;
        }

        if (eff == 0) {
            g_lutAB[bkt] = make_float2(s_a[idx0], s_b[idx0]);
        } else {
            // sid = # distinct flagged buckets < bkt. A bucket is flagged
            // iff it contains breakpoint j in [1, K-1]; s_bb is monotone.
            int sid = 0, prev = -1;
            for (int j = 1; j < K; j++) {
                int bb = s_bb[j];
                if (bb < bkt && bb != prev) { sid++; prev = bb; }
            }
            g_lutAB[bkt] = make_float2(__int_as_float(sid), QNAN);
            if (sid < MAXSID) {
                if (eff <= 2) {
                    if (eff == 1) { t2 = INF; g2 = g1; }
                    g_side[2 * sid]     = make_float4(t1, t2, s_a[g0], s_b[g0]);
                    g_side[2 * sid + 1] = make_float4(s_a[g1], s_b[g1], s_a[g2], s_b[g2]);
                } else {
                    g_side[2 * sid]     = make_float4(QNAN, QNAN, QNAN, QNAN);
                    g_side[2 * sid + 1] = make_float4(QNAN, QNAN, QNAN, QNAN);
                }
            }
        }
    }

    if (blockIdx.x == 0) {
        for (int i = t; i < K; i += blockDim.x) {
            g_sx[i] = s_sx[i];
            g_a[i]  = s_a[i];
            g_b[i]  = s_b[i];
        }
    }
}

// ---------------------------------------------------------------------------
// Main kernel — hot path: bucket FMA, LDS.64, FMA, clamp. Flagged elements
// resolved inline from a 4KB smem side table (no CALL, no search).
// ---------------------------------------------------------------------------
__device__ __forceinline__ float pwl_fast(float x, float scale, float offs,
                                          const float2* __restrict__ s_lut,
                                          bool& bad, float& tag) {
    int b = (int)fmaf(x, scale, offs);
    b = min(max(b, 0), NB - 1);
    float2 e = s_lut[b];
    bad = (e.y != e.y);            // NaN sentinel
    tag = e.x;                     // sid when flagged
    float y = fmaf(e.y, x, e.x);
    return fminf(fmaxf(y, 0.0f), 1.0f);
}

__device__ __forceinline__ float side_eval(float x, float tag,
                                           const float4* __restrict__ s_side,
                                           const float*  __restrict__ s_sx,
                                           const float*  __restrict__ s_a,
                                           const float*  __restrict__ s_b,
                                           int K) {
    int sid = min(__float_as_int(tag), MAXSID - 1);
    float4 A = s_side[2 * sid];
    float4 B = s_side[2 * sid + 1];
    float aa, bb;
    if (A.x == A.x) {                              // 1 or 2 exact splits
        int s = (x >= A.x) + (x >= A.y);           // INF compares false
        aa = (s == 0) ? A.z : ((s == 1) ? B.x : B.z);
        bb = (s == 0) ? A.w : ((s == 1) ? B.y : B.w);
    } else {                                       // >=3 splits: exact search
        int lo = 0, hi = K;
        while (lo < hi) {
            int mid = (lo + hi) >> 1;
            if (s_sx[mid] <= x) lo = mid + 1; else hi = mid;
        }
        int idx = min(max(lo, 1), K) - 1;
        aa = s_a[idx];
        bb = s_b[idx];
    }
    float y = fmaf(bb, x, aa);
    return fminf(fmaxf(y, 0.0f), 1.0f);
}

__global__ void __launch_bounds__(NTHR, 4)
pwl_main(const float* __restrict__ x, float* __restrict__ out, int n, int K) {
    __shared__ float2 s_lut[NB];
    __shared__ float4 s_side[2 * MAXSID];
    __shared__ float  s_sx[MAXK], s_a[MAXK], s_b[MAXK];

    for (int i = threadIdx.x; i < NB; i += NTHR) s_lut[i] = g_lutAB[i];
    for (int i = threadIdx.x; i < 2 * MAXSID; i += NTHR) s_side[i] = g_side[i];
    for (int i = threadIdx.x; i < MAXK; i += NTHR) {
        s_sx[i] = g_sx[i];
        s_a[i]  = g_a[i];
        s_b[i]  = g_b[i];
    }
    __syncthreads();

    const float scale = g_scale, offs = g_offs;
    const int n4 = n >> 2;
    const float4* __restrict__ x4 = (const float4*)x;
    float4* __restrict__ o4 = (float4*)out;
    const int stride = gridDim.x * NTHR;

    #pragma unroll 2
    for (int i = blockIdx.x * NTHR + threadIdx.x; i < n4; i += stride) {
        float4 v = x4[i];
        bool  b0, b1, b2, b3;
        float t0, t1, t2, t3;
        float4 r;
        r.x = pwl_fast(v.x, scale, offs, s_lut, b0, t0);
        r.y = pwl_fast(v.y, scale, offs, s_lut, b1, t1);
        r.z = pwl_fast(v.z, scale, offs, s_lut, b2, t2);
        r.w = pwl_fast(v.w, scale, offs, s_lut, b3, t3);
        if (b0 | b1 | b2 | b3) {               // inline, no CALL
            if (b0) r.x = side_eval(v.x, t0, s_side, s_sx, s_a, s_b, K);
            if (b1) r.y = side_eval(v.y, t1, s_side, s_sx, s_a, s_b, K);
            if (b2) r.z = side_eval(v.z, t2, s_side, s_sx, s_a, s_b, K);
            if (b3) r.w = side_eval(v.w, t3, s_side, s_sx, s_a, s_b, K);
        }
        o4[i] = r;
    }

    // Scalar tail
    int rem = n & 3;
    if (blockIdx.x == 0 && threadIdx.x < rem) {
        int i = (n4 << 2) + threadIdx.x;
        bool bad; float tag;
        float y = pwl_fast(x[i], scale, offs, s_lut, bad, tag);
        if (bad) y = side_eval(x[i], tag, s_side, s_sx, s_a, s_b, K);
        out[i] = y;
    }
}

// ---------------------------------------------------------------------------
extern "C" void kernel_launch(void* const* d_in, const int* in_sizes, int n_in,
                              void* d_out, int out_size) {
    const float* x      = (const float*)d_in[0];
    const float* xp     = (const float*)d_in[1];
    const float* slopes = (const float*)d_in[2];
    const float* biases = (const float*)d_in[3];
    int K = in_sizes[1];

    pwl_pre<<<PREBLK, PRETHR>>>(xp, slopes, biases, K);
    pwl_main<<<NBLK, NTHR>>>(x, (float*)d_out, out_size, K);
}